// round 16
// baseline (speedup 1.0000x reference)
#include <cuda_runtime.h>
#include <math.h>

// ---------------------------------------------------------------------------
// Sparse UNet block via tap-compacted dense gather-GEMMs (f32x2-packed FFMA).
//  - All 70 tap segments compacted in one kernel (ballot atomics, 8 elem/thr);
//    tile plan fused via last-block ticket.
//  - Each stage = ONE fused launch: persistent 592-block grid does BN stats,
//    last block finalizes scale/shift + bumps a generation counter, all blocks
//    spin, then run the tap-GEMM phase (R8 geometry: TP=128 pairs/tile,
//    thread tile 4 pairs x COUT/8 couts, fma.rn.f32x2 over cout pairs).
//  - Blocks take CONTIGUOUS tile ranges; W is cached in (dynamic) smem and
//    re-staged only on tap-segment change (kills per-tile W L2 traffic).
// ---------------------------------------------------------------------------

#define NMAX 200000
#define EPSF 1e-4f
#define TPAIR 128
#define STAGE_GRID 592
#define NSLOT 8

__device__ float g_buf[(size_t)NMAX * 64 * 3]; // cat | xc | xc2 (one memset)
__device__ int2  g_pf[27 * NMAX];
__device__ int2  g_pc[27 * NMAX];
__device__ int2  g_pd[8 * NMAX];
__device__ int2  g_pu[8 * NMAX];
__device__ int   g_cnt[70];            // 0..26 fine | 27..53 coarse | 54..61 down | 62..69 up
__device__ int   g_tb_f[28], g_tb_c[28], g_tb_d[9], g_tb_u[9];
__device__ double g_sums[NSLOT][128];
__device__ float g_scale[64];
__device__ float g_shift[64];
__device__ int   g_stick;              // stats ticket (per stage)
__device__ int   g_ctick;              // compact ticket
__device__ int   g_gen;                // stats generation counter (monotonic)

// ---------------------------------------------------------------------------
__global__ void prep_kernel() {
    int t = threadIdx.x;                       // 1024 threads
    ((double*)g_sums)[t] = 0.0;
    if (t < 70) g_cnt[t] = 0;
    if (t == 0) { g_stick = 0; g_ctick = 0; }
}

// ---------------------------------------------------------------------------
// One kernel compacts all 70 tap segments (8 elems/thread); last block
// computes the tile-plan prefix sums (tile size 128 everywhere).
__global__ void compact_all_kernel(const int* __restrict__ nf,
                                   const int* __restrict__ nc,
                                   const int* __restrict__ dn,
                                   const int* __restrict__ uci,
                                   const int* __restrict__ uk,
                                   int N, int M) {
    __shared__ bool lastsm;
    int seg = blockIdx.y;
    const int* src = nullptr; int nrows, sent = 0; int2* out; bool dec = false; int kd = 0;
    if (seg < 27)      { src = nf + (size_t)seg * N;        nrows = N; sent = N; out = g_pf + (size_t)seg * NMAX; }
    else if (seg < 54) { src = nc + (size_t)(seg - 27) * M; nrows = M; sent = M; out = g_pc + (size_t)(seg - 27) * NMAX; }
    else if (seg < 62) { src = dn + (size_t)(seg - 54) * M; nrows = M; sent = N; out = g_pd + (size_t)(seg - 54) * NMAX; }
    else               { nrows = N; out = g_pu + (size_t)(seg - 62) * NMAX; dec = true; kd = seg - 62; }
    int* cnt = &g_cnt[seg];
    int lane = threadIdx.x & 31;
    int base = (blockIdx.x * 256 + threadIdx.x) * 8;

    #pragma unroll
    for (int j = 0; j < 8; j++) {
        int r = base + j;
        int idx = 0; bool valid = false;
        if (r < nrows) {
            if (dec) { valid = (__ldg(uk + r) == kd); idx = __ldg(uci + r); }
            else     { idx = __ldg(src + r); valid = idx < sent; }
        }
        unsigned m = __ballot_sync(0xffffffffu, valid);
        if (m) {
            int ldr = __ffs(m) - 1;
            int pos = 0;
            if (lane == ldr) pos = atomicAdd(cnt, __popc(m));
            pos = __shfl_sync(0xffffffffu, pos, ldr);
            if (valid) out[pos + __popc(m & ((1u << lane) - 1))] = make_int2(r, idx);
        }
    }

    __threadfence();
    __syncthreads();
    if (threadIdx.x == 0) {
        int total = (int)(gridDim.x * gridDim.y);
        lastsm = (atomicAdd(&g_ctick, 1) == total - 1);
    }
    __syncthreads();

    if (lastsm) {
        __threadfence();
        int t = threadIdx.x;
        if (t < 4) {
            const int off0[5] = {0, 27, 54, 62, 70};
            int* tb = (t == 0) ? g_tb_f : (t == 1) ? g_tb_c : (t == 2) ? g_tb_d : g_tb_u;
            int s = 0;
            for (int k = off0[t]; k < off0[t + 1]; k++) {
                tb[k - off0[t]] = s;
                s += (g_cnt[k] + TPAIR - 1) / TPAIR;
            }
            tb[off0[t + 1] - off0[t]] = s;
        }
        if (threadIdx.x == 0) g_ctick = 0;
    }
}

// ---------------------------------------------------------------------------
__device__ __forceinline__ void red_add_v4(float* a, float x, float y, float z, float w) {
    asm volatile("red.global.add.v4.f32 [%0], {%1,%2,%3,%4};"
                 :: "l"(a), "f"(x), "f"(y), "f"(z), "f"(w) : "memory");
}
__device__ __forceinline__ unsigned long long pack2(float a) {
    unsigned long long r;
    asm("mov.b64 %0, {%1, %1};" : "=l"(r) : "r"(__float_as_uint(a)));
    return r;
}
__device__ __forceinline__ void fma2(unsigned long long& d,
                                     unsigned long long a, unsigned long long b) {
    asm("fma.rn.f32x2 %0, %1, %2, %0;" : "+l"(d) : "l"(a), "l"(b));
}
union U2F { unsigned long long u; float2 f; };

// ---------------------------------------------------------------------------
// Fused stage: BN stats over xin -> grid-wide handoff -> tap-GEMM.
// Dynamic smem: Wsm[CIN*COUT] | Asm[TPAIR*(CIN+2)].
// Contiguous tile chunk per block; W staged only on segment change.
template <int CIN, int COUT, bool DIRECT>
__global__ __launch_bounds__(256, 4)
void stage_kernel(const float* __restrict__ xin, int ld_in, int nrows,
                  const float* __restrict__ gw, const float* __restrict__ bw,
                  float inv_n,
                  const int2* __restrict__ pairs,
                  const int* __restrict__ cnt,
                  const int* __restrict__ tb, int K,
                  const float* __restrict__ W,
                  float* __restrict__ out, int ld_out) {
    constexpr int CP = CIN + 2;
    constexpr int CT = COUT / 8;    // couts per thread (4 or 8)
    constexpr int CU = CT / 2;      // packed accum width (2 or 4)
    constexpr int C4 = CIN / 4;

    extern __shared__ __align__(16) float smdyn[];
    float* Wsm = smdyn;                    // CIN*COUT floats
    float* Asm = smdyn + CIN * COUT;       // TPAIR*CP floats

    __shared__ int   rowsm[TPAIR];
    __shared__ int   idxsm[TPAIR];
    __shared__ float ssm[64], bsm[64];
    __shared__ int   tbsm[32], cntsm[32];
    __shared__ bool  lastsm;

    int tid = threadIdx.x;

    // ---------------- phase A: BN batch stats over xin ----------------
    {
        constexpr int TPR = CIN / 4;
        constexpr int RPB = 256 / TPR;
        float* smS = Asm;            // alias: 1024 floats
        float* smQ = Asm + 1024;     // alias: 1024 floats
        int tr = tid % TPR;
        int rg = tid / TPR;
        float4 s = make_float4(0.f, 0.f, 0.f, 0.f);
        float4 q = make_float4(0.f, 0.f, 0.f, 0.f);
        int stride = gridDim.x * RPB;
        #pragma unroll 4
        for (int r = blockIdx.x * RPB + rg; r < nrows; r += stride) {
            float4 v = __ldg((const float4*)(xin + (size_t)r * ld_in) + tr);
            s.x += v.x; s.y += v.y; s.z += v.z; s.w += v.w;
            q.x = fmaf(v.x, v.x, q.x); q.y = fmaf(v.y, v.y, q.y);
            q.z = fmaf(v.z, v.z, q.z); q.w = fmaf(v.w, v.w, q.w);
        }
        ((float4*)smS)[tid] = s;
        ((float4*)smQ)[tid] = q;
        __syncthreads();
        if (rg == 0) {
            #pragma unroll
            for (int j = 1; j < RPB; j++) {
                float4 a = ((float4*)smS)[j * TPR + tr];
                float4 b = ((float4*)smQ)[j * TPR + tr];
                s.x += a.x; s.y += a.y; s.z += a.z; s.w += a.w;
                q.x += b.x; q.y += b.y; q.z += b.z; q.w += b.w;
            }
            int slot = blockIdx.x & (NSLOT - 1);
            int c = tr * 4;
            atomicAdd(&g_sums[slot][c + 0], (double)s.x);
            atomicAdd(&g_sums[slot][c + 1], (double)s.y);
            atomicAdd(&g_sums[slot][c + 2], (double)s.z);
            atomicAdd(&g_sums[slot][c + 3], (double)s.w);
            atomicAdd(&g_sums[slot][64 + c + 0], (double)q.x);
            atomicAdd(&g_sums[slot][64 + c + 1], (double)q.y);
            atomicAdd(&g_sums[slot][64 + c + 2], (double)q.z);
            atomicAdd(&g_sums[slot][64 + c + 3], (double)q.w);
            __threadfence();
        }
        __syncthreads();

        // ticket; my-gen read precedes this block's ticket -> no lost wakeup
        int my = 0;
        if (tid == 0) {
            my = *(volatile int*)&g_gen;
            lastsm = (atomicAdd(&g_stick, 1) == (int)gridDim.x - 1);
        }
        __syncthreads();

        if (lastsm) {                  // finalize scale/shift
            __threadfence();
            int c = tid;
            if (c < 64) {
                double ss = 0.0, s2 = 0.0;
                #pragma unroll
                for (int j = 0; j < NSLOT; j++) {
                    ss += g_sums[j][c];      g_sums[j][c] = 0.0;
                    s2 += g_sums[j][64 + c]; g_sums[j][64 + c] = 0.0;
                }
                if (c < CIN) {
                    float mu  = (float)(ss * inv_n);
                    float var = (float)(s2 * inv_n) - mu * mu;
                    float inv = rsqrtf(var + EPSF);
                    float sc  = gw[c] * inv;
                    g_scale[c] = sc;
                    g_shift[c] = bw[c] - mu * sc;
                }
            }
            __syncthreads();
            if (tid == 0) {
                g_stick = 0;
                __threadfence();
                atomicAdd(&g_gen, 1);  // release
            }
        }

        if (tid == 0) {                // spin until this stage's gen bump
            while (*(volatile int*)&g_gen == my) __nanosleep(64);
            __threadfence();           // acquire
        }
        __syncthreads();
    }

    // ---------------- phase B: tap-GEMM ----------------
    if (tid < CIN) { ssm[tid] = g_scale[tid]; bsm[tid] = g_shift[tid]; }
    if (tid <= K)  tbsm[tid] = tb[tid];
    if (tid <  K)  cntsm[tid] = cnt[tid];
    __syncthreads();

    int total = tbsm[K];
    int tpb = (total + gridDim.x - 1) / gridDim.x;
    int t0b = blockIdx.x * tpb;
    int t1b = min(total, t0b + tpb);

    int tx = tid & 7;        // cout group
    int ty = tid >> 3;       // pair group (0..31)
    int pa = ty * 4;
    int k = 0, kprev = -1;

    for (int t = t0b; t < t1b; t++) {
        while (tbsm[k + 1] <= t) k++;
        int t0 = (t - tbsm[k]) * TPAIR;
        int np = min(TPAIR, cntsm[k] - t0);

        // stage W only on segment change (prev tile ended with a barrier)
        if (k != kprev) {
            const float4* Wg = (const float4*)(W + (size_t)k * CIN * COUT);
            for (int i = tid; i < CIN * COUT / 4; i += 256)
                ((float4*)Wsm)[i] = __ldg(&Wg[i]);
            kprev = k;
        }
        if (tid < TPAIR) {
            if (tid < np) {
                int2 pr = __ldg(&pairs[(size_t)k * NMAX + t0 + tid]);
                rowsm[tid] = pr.x; idxsm[tid] = pr.y;
            } else { rowsm[tid] = -1; idxsm[tid] = 0; }
        }
        __syncthreads();

        // gather + BN + ReLU into padded Asm
        for (int i = tid; i < TPAIR * C4; i += 256) {
            int p  = i / C4;
            int c4 = i % C4;
            float4 v = __ldg((const float4*)(xin + (size_t)idxsm[p] * ld_in) + c4);
            int c = c4 * 4;
            float* ap = &Asm[p * CP + c];
            ap[0] = fmaxf(fmaf(v.x, ssm[c + 0], bsm[c + 0]), 0.f);
            ap[1] = fmaxf(fmaf(v.y, ssm[c + 1], bsm[c + 1]), 0.f);
            ap[2] = fmaxf(fmaf(v.z, ssm[c + 2], bsm[c + 2]), 0.f);
            ap[3] = fmaxf(fmaf(v.w, ssm[c + 3], bsm[c + 3]), 0.f);
        }
        __syncthreads();

        // packed register-tiled GEMM
        unsigned long long acc[4][CU];
        #pragma unroll
        for (int i = 0; i < 4; i++)
            #pragma unroll
            for (int j = 0; j < CU; j++) acc[i][j] = 0ull;

        const float* a0p = &Asm[pa * CP];
        #pragma unroll 8
        for (int c = 0; c < CIN; c++) {
            unsigned long long aa0 = pack2(a0p[c]);
            unsigned long long aa1 = pack2(a0p[CP + c]);
            unsigned long long aa2 = pack2(a0p[2 * CP + c]);
            unsigned long long aa3 = pack2(a0p[3 * CP + c]);
            const ulonglong2* wr = (const ulonglong2*)&Wsm[c * COUT + tx * CT];
            #pragma unroll
            for (int j = 0; j < CU / 2; j++) {
                ulonglong2 w2 = wr[j];
                fma2(acc[0][2*j], aa0, w2.x); fma2(acc[0][2*j+1], aa0, w2.y);
                fma2(acc[1][2*j], aa1, w2.x); fma2(acc[1][2*j+1], aa1, w2.y);
                fma2(acc[2][2*j], aa2, w2.x); fma2(acc[2][2*j+1], aa2, w2.y);
                fma2(acc[3][2*j], aa3, w2.x); fma2(acc[3][2*j+1], aa3, w2.y);
            }
        }

        // write back
        #pragma unroll
        for (int i = 0; i < 4; i++) {
            int r = rowsm[pa + i];
            if (r >= 0) {
                float* op = out + (size_t)r * ld_out + tx * CT;
                #pragma unroll
                for (int j2 = 0; j2 < CU / 2; j2++) {
                    U2F u0, u1; u0.u = acc[i][2 * j2]; u1.u = acc[i][2 * j2 + 1];
                    if (DIRECT) {
                        *(float4*)(op + 4 * j2) =
                            make_float4(u0.f.x, u0.f.y, u1.f.x, u1.f.y);
                    } else {
                        red_add_v4(op + 4 * j2, u0.f.x, u0.f.y, u1.f.x, u1.f.y);
                    }
                }
            }
        }
        __syncthreads();
    }
}

// ---------------------------------------------------------------------------
static inline int smem_bytes(int cin, int cout) {
    return (cin * cout + TPAIR * (cin + 2)) * 4;
}

extern "C" void kernel_launch(void* const* d_in, const int* in_sizes, int n_in,
                              void* d_out, int out_size) {
    const float* feat    = (const float*)d_in[0];
    const float* w_sub1  = (const float*)d_in[1];
    const float* w_down  = (const float*)d_in[2];
    const float* w_sub2  = (const float*)d_in[3];
    const float* w_up    = (const float*)d_in[4];
    const float* w_sub3  = (const float*)d_in[5];
    const float* g1 = (const float*)d_in[6];  const float* b1 = (const float*)d_in[7];
    const float* g2 = (const float*)d_in[8];  const float* b2 = (const float*)d_in[9];
    const float* g3 = (const float*)d_in[10]; const float* b3 = (const float*)d_in[11];
    const float* g4 = (const float*)d_in[12]; const float* b4 = (const float*)d_in[13];
    const float* g5 = (const float*)d_in[14]; const float* b5 = (const float*)d_in[15];
    const int* nbr_fine   = (const int*)d_in[16];
    const int* nbr_coarse = (const int*)d_in[17];
    const int* down_idx   = (const int*)d_in[18];
    const int* up_cidx    = (const int*)d_in[19];
    const int* up_k       = (const int*)d_in[20];

    const int N = in_sizes[0] / 32;
    const int M = in_sizes[18] / 8;

    float* buf;
    int *cnt_ptr, *tbf, *tbc, *tbd, *tbu;
    cudaGetSymbolAddress((void**)&buf, g_buf);
    cudaGetSymbolAddress((void**)&cnt_ptr, g_cnt);
    cudaGetSymbolAddress((void**)&tbf, g_tb_f);
    cudaGetSymbolAddress((void**)&tbc, g_tb_c);
    cudaGetSymbolAddress((void**)&tbd, g_tb_d);
    cudaGetSymbolAddress((void**)&tbu, g_tb_u);
    int2 *pf, *pc, *pd, *pu;
    cudaGetSymbolAddress((void**)&pf, g_pf);
    cudaGetSymbolAddress((void**)&pc, g_pc);
    cudaGetSymbolAddress((void**)&pd, g_pd);
    cudaGetSymbolAddress((void**)&pu, g_pu);

    float* cat_ptr = buf;
    float* xc_ptr  = buf + (size_t)NMAX * 64;
    float* xc2_ptr = buf + (size_t)NMAX * 64 * 2;

    // raise dynamic smem limits (idempotent, capture-safe host calls)
    cudaFuncSetAttribute((const void*)stage_kernel<32, 32, false>,
                         cudaFuncAttributeMaxDynamicSharedMemorySize, smem_bytes(32, 32));
    cudaFuncSetAttribute((const void*)stage_kernel<32, 64, false>,
                         cudaFuncAttributeMaxDynamicSharedMemorySize, smem_bytes(32, 64));
    cudaFuncSetAttribute((const void*)stage_kernel<64, 64, false>,
                         cudaFuncAttributeMaxDynamicSharedMemorySize, smem_bytes(64, 64));
    cudaFuncSetAttribute((const void*)stage_kernel<64, 32, true>,
                         cudaFuncAttributeMaxDynamicSharedMemorySize, smem_bytes(64, 32));
    cudaFuncSetAttribute((const void*)stage_kernel<64, 32, false>,
                         cudaFuncAttributeMaxDynamicSharedMemorySize, smem_bytes(64, 32));

    // zero accumulation targets (cat/xc/xc2 contiguous -> one memset)
    cudaMemsetAsync(buf, 0, ((size_t)N * 64 +
                             (size_t)(NMAX + M) * 64) * sizeof(float));
    cudaMemsetAsync(d_out, 0, (size_t)out_size * sizeof(float));

    // geometry prep: counters, compaction + fused tile plan
    prep_kernel<<<1, 1024>>>();
    int mx = (N > M ? N : M);
    dim3 cg((mx + 2047) / 2048, 70);
    compact_all_kernel<<<cg, 256>>>(nbr_fine, nbr_coarse, down_idx, up_cidx, up_k, N, M);

    // stage 1: BN(feat) + subconv1 (32->32, fine taps) into cat[:,0:32]
    stage_kernel<32, 32, false><<<STAGE_GRID, 256, smem_bytes(32, 32)>>>(
        feat, 32, N, g1, b1, 1.0f / N,
        pf, cnt_ptr + 0, tbf, 27, w_sub1, cat_ptr, 64);

    // stage 2: BN(skip) + down conv (32->64) into xc
    stage_kernel<32, 64, false><<<STAGE_GRID, 256, smem_bytes(32, 64)>>>(
        cat_ptr, 64, N, g2, b2, 1.0f / N,
        pd, cnt_ptr + 54, tbd, 8, w_down, xc_ptr, 64);

    // stage 3: BN(xc) + subconv2 (64->64, coarse taps) into xc2
    stage_kernel<64, 64, false><<<STAGE_GRID, 256, smem_bytes(64, 64)>>>(
        xc_ptr, 64, M, g3, b3, 1.0f / M,
        pc, cnt_ptr + 27, tbc, 27, w_sub2, xc2_ptr, 64);

    // stage 4: BN(xc2) + deconv (64->32) direct into cat[:,32:64]
    stage_kernel<64, 32, true><<<STAGE_GRID, 256, smem_bytes(64, 32)>>>(
        xc2_ptr, 64, M, g4, b4, 1.0f / M,
        pu, cnt_ptr + 62, tbu, 8, w_up, cat_ptr + 32, 64);

    // stage 5: BN(cat) + subconv3 (64->32, fine taps) into out
    stage_kernel<64, 32, false><<<STAGE_GRID, 256, smem_bytes(64, 32)>>>(
        cat_ptr, 64, N, g5, b5, 1.0f / N,
        pf, cnt_ptr + 0, tbf, 27, w_sub3, (float*)d_out, 32);
}